// round 1
// baseline (speedup 1.0000x reference)
#include <cuda_runtime.h>
#include <cuda_bf16.h>

// Problem: B=128, T=512, E=8, H=2, dk=4. N = B*T = 65536 rows.
#define TT 512
#define NROWS (128*512)

// Scratch: attention context, (B,T,8) float
__device__ float g_ctx[NROWS * 8];

// qlayer closed form: given c[w] = cos(alpha_w), outputs:
// out[0] = c1*c2*...*c7 ; out[w>=1] = c0*c1*...*cw
__device__ __forceinline__ void qlayer_from_cos(const float c[8], float o[8]) {
    float t = c[1] * c[2];
    t *= c[3]; t *= c[4]; t *= c[5]; t *= c[6]; t *= c[7];
    o[0] = t;
    float p = c[0] * c[1];
    o[1] = p;
    p *= c[2]; o[2] = p;
    p *= c[3]; o[3] = p;
    p *= c[4]; o[4] = p;
    p *= c[5]; o[5] = p;
    p *= c[6]; o[6] = p;
    p *= c[7]; o[7] = p;
}

// ---------------------------------------------------------------------------
// Kernel 1: fused qkv (closed-form qlayer on x) + attention for one (b, h).
// grid = B*H = 256 blocks, block = T = 512 threads. Thread t = query row t.
// ---------------------------------------------------------------------------
__global__ __launch_bounds__(512) void attn_kernel(
    const float* __restrict__ x,          // (B,T,8)
    const float* __restrict__ thetas_attn // (8,)
) {
    const int bh = blockIdx.x;
    const int b  = bh >> 1;
    const int h  = bh & 1;
    const int t  = threadIdx.x;

    __shared__ float4 Ksh[TT];

    const float* xr = x + ((size_t)(b * TT + t)) * 8;
    float4 xa = *reinterpret_cast<const float4*>(xr);
    float4 xb = *reinterpret_cast<const float4*>(xr + 4);

    float c[8];
    c[0] = cosf(xa.x + thetas_attn[0]);
    c[1] = cosf(xa.y + thetas_attn[1]);
    c[2] = cosf(xa.z + thetas_attn[2]);
    c[3] = cosf(xa.w + thetas_attn[3]);
    c[4] = cosf(xb.x + thetas_attn[4]);
    c[5] = cosf(xb.y + thetas_attn[5]);
    c[6] = cosf(xb.z + thetas_attn[6]);
    c[7] = cosf(xb.w + thetas_attn[7]);

    float o[8];
    qlayer_from_cos(c, o);

    float4 q = (h == 0) ? make_float4(o[0], o[1], o[2], o[3])
                        : make_float4(o[4], o[5], o[6], o[7]);
    Ksh[t] = q;
    __syncthreads();

    // Online softmax without max subtraction: entries of h are products of
    // cosines in [-1,1], so |score| = |dot|/sqrt(4) <= 4*0.5 = 2. exp safe.
    float denom = 0.0f;
    float ax = 0.0f, ay = 0.0f, az = 0.0f, aw = 0.0f;
#pragma unroll 8
    for (int k = 0; k < TT; k++) {
        float4 kk = Ksh[k];
        float s = q.x * kk.x + q.y * kk.y + q.z * kk.z + q.w * kk.w;
        float e = __expf(0.5f * s);
        denom += e;
        ax += e * kk.x;
        ay += e * kk.y;
        az += e * kk.z;
        aw += e * kk.w;
    }
    float inv = 1.0f / denom;
    float4 ctx = make_float4(ax * inv, ay * inv, az * inv, aw * inv);
    // ctx transposed back: row (b,t), columns [4h, 4h+4)
    *reinterpret_cast<float4*>(g_ctx + ((size_t)(b * TT + t)) * 8 + h * 4) = ctx;
}

// ---------------------------------------------------------------------------
// Kernel 2: per-row epilogue.
//   attn_out = qlayer_attn(ctx); x1 = LN1(attn_out + x);
//   hq = x1 @ W_in^T + b_in; q = qlayer_ffn(hq) (wires [0,1,2,2,4,5,6,7]);
//   ff = q @ W_out^T + b_out; out = LN2(ff + x1)
// One thread per row.
// ---------------------------------------------------------------------------
__global__ __launch_bounds__(256) void rest_kernel(
    const float* __restrict__ x,
    const float* __restrict__ thetas_attn,
    const float* __restrict__ thetas_ffn,
    const float* __restrict__ W_in,
    const float* __restrict__ b_in,
    const float* __restrict__ W_out,
    const float* __restrict__ b_out,
    const float* __restrict__ ln1w, const float* __restrict__ ln1b,
    const float* __restrict__ ln2w, const float* __restrict__ ln2b,
    float* __restrict__ out
) {
    __shared__ float sWin[64], sWout[64];
    __shared__ float sbin[8], sbout[8], s1w[8], s1b[8], s2w[8], s2b[8],
                     stha[8], sthf[8];
    int tx = threadIdx.x;
    if (tx < 64) { sWin[tx] = W_in[tx]; sWout[tx] = W_out[tx]; }
    if (tx < 8) {
        sbin[tx]  = b_in[tx];       sbout[tx] = b_out[tx];
        s1w[tx]   = ln1w[tx];       s1b[tx]   = ln1b[tx];
        s2w[tx]   = ln2w[tx];       s2b[tx]   = ln2b[tx];
        stha[tx]  = thetas_attn[tx]; sthf[tx] = thetas_ffn[tx];
    }
    __syncthreads();

    int r = blockIdx.x * blockDim.x + tx;

    const float* cr = g_ctx + (size_t)r * 8;
    const float* xr = x + (size_t)r * 8;
    float ctx[8], xv[8];
    {
        float4 a = *reinterpret_cast<const float4*>(cr);
        float4 bb = *reinterpret_cast<const float4*>(cr + 4);
        ctx[0]=a.x; ctx[1]=a.y; ctx[2]=a.z; ctx[3]=a.w;
        ctx[4]=bb.x; ctx[5]=bb.y; ctx[6]=bb.z; ctx[7]=bb.w;
        float4 e = *reinterpret_cast<const float4*>(xr);
        float4 f = *reinterpret_cast<const float4*>(xr + 4);
        xv[0]=e.x; xv[1]=e.y; xv[2]=e.z; xv[3]=e.w;
        xv[4]=f.x; xv[5]=f.y; xv[6]=f.z; xv[7]=f.w;
    }

    // attn qlayer on ctx
    float c[8];
#pragma unroll
    for (int w = 0; w < 8; w++) c[w] = cosf(ctx[w] + stha[w]);
    float ao[8];
    qlayer_from_cos(c, ao);

    // x1 = LN1(ao + x)
    float s[8], x1[8];
    float m = 0.0f;
#pragma unroll
    for (int w = 0; w < 8; w++) { s[w] = ao[w] + xv[w]; m += s[w]; }
    m *= 0.125f;
    float v = 0.0f;
#pragma unroll
    for (int w = 0; w < 8; w++) { float d = s[w] - m; v += d * d; }
    v *= 0.125f;
    float istd = rsqrtf(v + 1e-5f);
#pragma unroll
    for (int w = 0; w < 8; w++) x1[w] = (s[w] - m) * istd * s1w[w] + s1b[w];

    // hq = x1 @ W_in^T + b_in
    float hq[8];
#pragma unroll
    for (int i = 0; i < 8; i++) {
        float acc = sbin[i];
#pragma unroll
        for (int j = 0; j < 8; j++) acc += x1[j] * sWin[i * 8 + j];
        hq[i] = acc;
    }

    // ffn qlayer, wires [0,1,2,2,4,5,6,7]:
    //   a0=hq0+th0, a1=hq1+th1, a2=hq2+hq3+th2, a3=th3, a4..7=hq_w+th_w
    float cf[8];
    cf[0] = cosf(hq[0] + sthf[0]);
    cf[1] = cosf(hq[1] + sthf[1]);
    cf[2] = cosf(hq[2] + hq[3] + sthf[2]);
    cf[3] = cosf(sthf[3]);
    cf[4] = cosf(hq[4] + sthf[4]);
    cf[5] = cosf(hq[5] + sthf[5]);
    cf[6] = cosf(hq[6] + sthf[6]);
    cf[7] = cosf(hq[7] + sthf[7]);
    float qf[8];
    qlayer_from_cos(cf, qf);

    // ff = qf @ W_out^T + b_out; s2 = ff + x1; out = LN2(s2)
    float s2[8];
    float m2 = 0.0f;
#pragma unroll
    for (int i = 0; i < 8; i++) {
        float acc = sbout[i];
#pragma unroll
        for (int j = 0; j < 8; j++) acc += qf[j] * sWout[i * 8 + j];
        s2[i] = acc + x1[i];
        m2 += s2[i];
    }
    m2 *= 0.125f;
    float v2 = 0.0f;
#pragma unroll
    for (int i = 0; i < 8; i++) { float d = s2[i] - m2; v2 += d * d; }
    v2 *= 0.125f;
    float istd2 = rsqrtf(v2 + 1e-5f);

    float res[8];
#pragma unroll
    for (int i = 0; i < 8; i++)
        res[i] = (s2[i] - m2) * istd2 * s2w[i] + s2b[i];

    float* orow = out + (size_t)r * 8;
    *reinterpret_cast<float4*>(orow)     = make_float4(res[0], res[1], res[2], res[3]);
    *reinterpret_cast<float4*>(orow + 4) = make_float4(res[4], res[5], res[6], res[7]);
}

extern "C" void kernel_launch(void* const* d_in, const int* in_sizes, int n_in,
                              void* d_out, int out_size) {
    const float* x           = (const float*)d_in[0];
    const float* thetas_attn = (const float*)d_in[1];
    const float* thetas_ffn  = (const float*)d_in[2];
    const float* W_in        = (const float*)d_in[3];
    const float* b_in        = (const float*)d_in[4];
    const float* W_out       = (const float*)d_in[5];
    const float* b_out       = (const float*)d_in[6];
    const float* ln1w        = (const float*)d_in[7];
    const float* ln1b        = (const float*)d_in[8];
    const float* ln2w        = (const float*)d_in[9];
    const float* ln2b        = (const float*)d_in[10];
    float* out = (float*)d_out;

    attn_kernel<<<256, 512>>>(x, thetas_attn);
    rest_kernel<<<NROWS / 256, 256>>>(x, thetas_attn, thetas_ffn,
                                      W_in, b_in, W_out, b_out,
                                      ln1w, ln1b, ln2w, ln2b, out);
}

// round 2
// speedup vs baseline: 1.2581x; 1.2581x over previous
#include <cuda_runtime.h>
#include <cuda_bf16.h>

// Problem: B=128, T=512, E=8, H=2, dk=4. N = B*T = 65536 rows.
#define TT 512
#define NROWS (128*512)
#define QC 128          // queries per block in attn kernel

// Scratch: attention context, (B,T,8) float
__device__ float g_ctx[NROWS * 8];

// ---- f32x2 packed helpers (sm_103a FFMA2 only reachable via PTX) ----------
__device__ __forceinline__ unsigned long long pack2(float lo, float hi) {
    unsigned long long r;
    asm("mov.b64 %0, {%1, %2};" : "=l"(r) : "f"(lo), "f"(hi));
    return r;
}
__device__ __forceinline__ void unpack2(unsigned long long v, float& lo, float& hi) {
    asm("mov.b64 {%0, %1}, %2;" : "=f"(lo), "=f"(hi) : "l"(v));
}
__device__ __forceinline__ unsigned long long mul2(unsigned long long a, unsigned long long b) {
    unsigned long long r;
    asm("mul.rn.f32x2 %0, %1, %2;" : "=l"(r) : "l"(a), "l"(b));
    return r;
}
__device__ __forceinline__ unsigned long long fma2(unsigned long long a, unsigned long long b,
                                                   unsigned long long c) {
    unsigned long long r;
    asm("fma.rn.f32x2 %0, %1, %2, %3;" : "=l"(r) : "l"(a), "l"(b), "l"(c));
    return r;
}
__device__ __forceinline__ float ex2(float x) {
    float r;
    asm("ex2.approx.ftz.f32 %0, %1;" : "=f"(r) : "f"(x));
    return r;
}

// qlayer closed form: given c[w] = cos(alpha_w):
// out[0] = c1*c2*...*c7 ; out[w>=1] = c0*c1*...*cw
__device__ __forceinline__ void qlayer_from_cos(const float c[8], float o[8]) {
    float t = c[1] * c[2];
    t *= c[3]; t *= c[4]; t *= c[5]; t *= c[6]; t *= c[7];
    o[0] = t;
    float p = c[0] * c[1];
    o[1] = p;
    p *= c[2]; o[2] = p;
    p *= c[3]; o[3] = p;
    p *= c[4]; o[4] = p;
    p *= c[5]; o[5] = p;
    p *= c[6]; o[6] = p;
    p *= c[7]; o[7] = p;
}

// ---------------------------------------------------------------------------
// Kernel 1: fused qkv (closed-form qlayer) + attention.
// grid = B*H*(T/QC) = 1024 blocks, block = QC = 128 threads.
// Block handles QC queries of one (b,h); prologue regenerates all 512 keys.
// ---------------------------------------------------------------------------
__global__ __launch_bounds__(QC) void attn_kernel(
    const float* __restrict__ x,          // (B,T,8)
    const float* __restrict__ thetas_attn // (8,)
) {
    const int blk   = blockIdx.x;
    const int bh    = blk >> 2;      // 4 chunks per (b,h)
    const int chunk = blk & 3;
    const int b = bh >> 1;
    const int h = bh & 1;
    const int tid = threadIdx.x;

    __shared__ ulonglong2 Ksh[TT];   // key vectors, packed as 2x f32x2

    float th[8];
#pragma unroll
    for (int w = 0; w < 8; w++) th[w] = thetas_attn[w];

    // Prologue: each thread builds 4 key rows (head h's 4 dims).
#pragma unroll
    for (int rr = 0; rr < TT / QC; rr++) {
        int i = tid + rr * QC;
        const float* xr = x + ((size_t)(b * TT + i)) * 8;
        float4 xa = *reinterpret_cast<const float4*>(xr);
        float4 xb = *reinterpret_cast<const float4*>(xr + 4);
        float c[8];
        c[0] = __cosf(xa.x + th[0]);
        c[1] = __cosf(xa.y + th[1]);
        c[2] = __cosf(xa.z + th[2]);
        c[3] = __cosf(xa.w + th[3]);
        c[4] = __cosf(xb.x + th[4]);
        c[5] = __cosf(xb.y + th[5]);
        c[6] = __cosf(xb.z + th[6]);
        c[7] = __cosf(xb.w + th[7]);
        float o[8];
        qlayer_from_cos(c, o);
        ulonglong2 kk;
        if (h == 0) { kk.x = pack2(o[0], o[1]); kk.y = pack2(o[2], o[3]); }
        else        { kk.x = pack2(o[4], o[5]); kk.y = pack2(o[6], o[7]); }
        Ksh[i] = kk;
    }
    __syncthreads();

    const int qi = chunk * QC + tid;
    ulonglong2 qk = Ksh[qi];
    float q0, q1, q2, q3;
    unpack2(qk.x, q0, q1);
    unpack2(qk.y, q2, q3);

    // Pre-scale q by 0.5 * log2(e): exp(0.5*q.k) = exp2((Sq).k)
    const float SC = 0.72134752044f;
    unsigned long long qs01 = pack2(q0 * SC, q1 * SC);
    unsigned long long qs23 = pack2(q2 * SC, q3 * SC);

    unsigned long long acc01 = 0ull, acc23 = 0ull;
    float denom = 0.0f;

    // |score*0.5| <= 2, exp2 arg bounded: no max subtraction needed.
#pragma unroll 8
    for (int k = 0; k < TT; k++) {
        ulonglong2 kk = Ksh[k];
        unsigned long long p = mul2(qs01, kk.x);
        p = fma2(qs23, kk.y, p);
        float lo, hi;
        unpack2(p, lo, hi);
        float e = ex2(lo + hi);
        unsigned long long e2 = pack2(e, e);
        acc01 = fma2(e2, kk.x, acc01);
        acc23 = fma2(e2, kk.y, acc23);
        denom += e;
    }

    float inv = __fdividef(1.0f, denom);
    float a0, a1, a2, a3;
    unpack2(acc01, a0, a1);
    unpack2(acc23, a2, a3);
    // ctx row (b, qi), columns [4h, 4h+4)
    *reinterpret_cast<float4*>(g_ctx + ((size_t)(b * TT + qi)) * 8 + h * 4) =
        make_float4(a0 * inv, a1 * inv, a2 * inv, a3 * inv);
}

// ---------------------------------------------------------------------------
// Kernel 2: per-row epilogue. One thread per row.
// ---------------------------------------------------------------------------
__global__ __launch_bounds__(256) void rest_kernel(
    const float* __restrict__ x,
    const float* __restrict__ thetas_attn,
    const float* __restrict__ thetas_ffn,
    const float* __restrict__ W_in,
    const float* __restrict__ b_in,
    const float* __restrict__ W_out,
    const float* __restrict__ b_out,
    const float* __restrict__ ln1w, const float* __restrict__ ln1b,
    const float* __restrict__ ln2w, const float* __restrict__ ln2b,
    float* __restrict__ out
) {
    __shared__ float sWin[64], sWout[64];
    __shared__ float sbin[8], sbout[8], s1w[8], s1b[8], s2w[8], s2b[8],
                     stha[8], sthf[8];
    int tx = threadIdx.x;
    if (tx < 64) { sWin[tx] = W_in[tx]; sWout[tx] = W_out[tx]; }
    if (tx < 8) {
        sbin[tx]  = b_in[tx];        sbout[tx] = b_out[tx];
        s1w[tx]   = ln1w[tx];        s1b[tx]   = ln1b[tx];
        s2w[tx]   = ln2w[tx];        s2b[tx]   = ln2b[tx];
        stha[tx]  = thetas_attn[tx]; sthf[tx]  = thetas_ffn[tx];
    }
    __syncthreads();

    int r = blockIdx.x * blockDim.x + tx;

    const float* cr = g_ctx + (size_t)r * 8;
    const float* xr = x + (size_t)r * 8;
    float ctx[8], xv[8];
    {
        float4 a  = *reinterpret_cast<const float4*>(cr);
        float4 bb = *reinterpret_cast<const float4*>(cr + 4);
        ctx[0]=a.x;  ctx[1]=a.y;  ctx[2]=a.z;  ctx[3]=a.w;
        ctx[4]=bb.x; ctx[5]=bb.y; ctx[6]=bb.z; ctx[7]=bb.w;
        float4 e = *reinterpret_cast<const float4*>(xr);
        float4 f = *reinterpret_cast<const float4*>(xr + 4);
        xv[0]=e.x; xv[1]=e.y; xv[2]=e.z; xv[3]=e.w;
        xv[4]=f.x; xv[5]=f.y; xv[6]=f.z; xv[7]=f.w;
    }

    // attn qlayer on ctx
    float c[8];
#pragma unroll
    for (int w = 0; w < 8; w++) c[w] = __cosf(ctx[w] + stha[w]);
    float ao[8];
    qlayer_from_cos(c, ao);

    // x1 = LN1(ao + x)
    float s[8], x1[8];
    float m = 0.0f;
#pragma unroll
    for (int w = 0; w < 8; w++) { s[w] = ao[w] + xv[w]; m += s[w]; }
    m *= 0.125f;
    float v = 0.0f;
#pragma unroll
    for (int w = 0; w < 8; w++) { float d = s[w] - m; v += d * d; }
    v *= 0.125f;
    float istd = rsqrtf(v + 1e-5f);
#pragma unroll
    for (int w = 0; w < 8; w++) x1[w] = (s[w] - m) * istd * s1w[w] + s1b[w];

    // hq = x1 @ W_in^T + b_in
    float hq[8];
#pragma unroll
    for (int i = 0; i < 8; i++) {
        float acc = sbin[i];
#pragma unroll
        for (int j = 0; j < 8; j++) acc += x1[j] * sWin[i * 8 + j];
        hq[i] = acc;
    }

    // ffn qlayer, wires [0,1,2,2,4,5,6,7]:
    //   a0=hq0+th0, a1=hq1+th1, a2=hq2+hq3+th2, a3=th3, a4..7=hq_w+th_w
    float cf[8];
    cf[0] = __cosf(hq[0] + sthf[0]);
    cf[1] = __cosf(hq[1] + sthf[1]);
    cf[2] = __cosf(hq[2] + hq[3] + sthf[2]);
    cf[3] = __cosf(sthf[3]);
    cf[4] = __cosf(hq[4] + sthf[4]);
    cf[5] = __cosf(hq[5] + sthf[5]);
    cf[6] = __cosf(hq[6] + sthf[6]);
    cf[7] = __cosf(hq[7] + sthf[7]);
    float qf[8];
    qlayer_from_cos(cf, qf);

    // ff = qf @ W_out^T + b_out; s2 = ff + x1; out = LN2(s2)
    float s2[8];
    float m2 = 0.0f;
#pragma unroll
    for (int i = 0; i < 8; i++) {
        float acc = sbout[i];
#pragma unroll
        for (int j = 0; j < 8; j++) acc += qf[j] * sWout[i * 8 + j];
        s2[i] = acc + x1[i];
        m2 += s2[i];
    }
    m2 *= 0.125f;
    float v2 = 0.0f;
#pragma unroll
    for (int i = 0; i < 8; i++) { float d = s2[i] - m2; v2 += d * d; }
    v2 *= 0.125f;
    float istd2 = rsqrtf(v2 + 1e-5f);

    float res[8];
#pragma unroll
    for (int i = 0; i < 8; i++)
        res[i] = (s2[i] - m2) * istd2 * s2w[i] + s2b[i];

    float* orow = out + (size_t)r * 8;
    *reinterpret_cast<float4*>(orow)     = make_float4(res[0], res[1], res[2], res[3]);
    *reinterpret_cast<float4*>(orow + 4) = make_float4(res[4], res[5], res[6], res[7]);
}

extern "C" void kernel_launch(void* const* d_in, const int* in_sizes, int n_in,
                              void* d_out, int out_size) {
    const float* x           = (const float*)d_in[0];
    const float* thetas_attn = (const float*)d_in[1];
    const float* thetas_ffn  = (const float*)d_in[2];
    const float* W_in        = (const float*)d_in[3];
    const float* b_in        = (const float*)d_in[4];
    const float* W_out       = (const float*)d_in[5];
    const float* b_out       = (const float*)d_in[6];
    const float* ln1w        = (const float*)d_in[7];
    const float* ln1b        = (const float*)d_in[8];
    const float* ln2w        = (const float*)d_in[9];
    const float* ln2b        = (const float*)d_in[10];
    float* out = (float*)d_out;

    attn_kernel<<<(128 * 2 * (TT / QC)), QC>>>(x, thetas_attn);
    rest_kernel<<<NROWS / 256, 256>>>(x, thetas_attn, thetas_ffn,
                                      W_in, b_in, W_out, b_out,
                                      ln1w, ln1b, ln2w, ln2b, out);
}

// round 3
// speedup vs baseline: 1.3368x; 1.0626x over previous
#include <cuda_runtime.h>
#include <cuda_bf16.h>

// Problem: B=128, T=512, E=8, H=2, dk=4. N = B*T = 65536 rows.
#define TT 512
#define QC 64           // queries per block (2 threads per query)
#define NBLK (128 * (TT / QC))   // 1024 blocks

typedef unsigned long long u64;

// ---- f32x2 packed helpers (sm_103a FFMA2 only reachable via PTX) ----------
__device__ __forceinline__ u64 pack2(float lo, float hi) {
    u64 r; asm("mov.b64 %0, {%1, %2};" : "=l"(r) : "f"(lo), "f"(hi)); return r;
}
__device__ __forceinline__ void unpack2(u64 v, float& lo, float& hi) {
    asm("mov.b64 {%0, %1}, %2;" : "=f"(lo), "=f"(hi) : "l"(v));
}
__device__ __forceinline__ u64 mul2(u64 a, u64 b) {
    u64 r; asm("mul.rn.f32x2 %0, %1, %2;" : "=l"(r) : "l"(a), "l"(b)); return r;
}
__device__ __forceinline__ u64 fma2(u64 a, u64 b, u64 c) {
    u64 r; asm("fma.rn.f32x2 %0, %1, %2, %3;" : "=l"(r) : "l"(a), "l"(b), "l"(c)); return r;
}
__device__ __forceinline__ u64 add2(u64 a, u64 b) {
    u64 r; asm("add.rn.f32x2 %0, %1, %2;" : "=l"(r) : "l"(a), "l"(b)); return r;
}
__device__ __forceinline__ float ex2(float x) {
    float r; asm("ex2.approx.ftz.f32 %0, %1;" : "=f"(r) : "f"(x)); return r;
}

// qlayer closed form: given c[w] = cos(alpha_w):
// out[0] = c1*...*c7 ; out[w>=1] = c0*...*cw
__device__ __forceinline__ void qlayer_from_cos(const float c[8], float o[8]) {
    float t = c[1] * c[2];
    t *= c[3]; t *= c[4]; t *= c[5]; t *= c[6]; t *= c[7];
    o[0] = t;
    float p = c[0] * c[1];
    o[1] = p;
    p *= c[2]; o[2] = p;
    p *= c[3]; o[3] = p;
    p *= c[4]; o[4] = p;
    p *= c[5]; o[5] = p;
    p *= c[6]; o[6] = p;
    p *= c[7]; o[7] = p;
}

// ---------------------------------------------------------------------------
// Fully fused kernel. grid = 1024, block = 128.
// Block = (batch b, query chunk of 64). Each query handled by 2 threads
// (key halves of 256), both heads packed in f32x2 lanes. Even lane of each
// pair runs the entire epilogue (qlayer, LN1, matvec, qlayer_ffn, matvec, LN2).
// ---------------------------------------------------------------------------
__global__ __launch_bounds__(128, 7) void fused_kernel(
    const float* __restrict__ x,
    const float* __restrict__ thetas_attn,
    const float* __restrict__ thetas_ffn,
    const float* __restrict__ W_in,
    const float* __restrict__ b_in,
    const float* __restrict__ W_out,
    const float* __restrict__ b_out,
    const float* __restrict__ ln1w, const float* __restrict__ ln1b,
    const float* __restrict__ ln2w, const float* __restrict__ ln2b,
    float* __restrict__ out
) {
    // Keys: per key 4 x f32x2, lane-packed (dim_i of head0, dim_i of head1)
    __shared__ ulonglong2 Kpk[TT][2];
    __shared__ float sWin[64], sWout[64];
    __shared__ float sbin[8], sbout[8], s1w[8], s1b[8], s2w[8], s2b[8],
                     stha[8], sthf[8];

    const int tid   = threadIdx.x;
    const int b     = blockIdx.x >> 3;
    const int chunk = blockIdx.x & 7;

    if (tid < 64) { sWin[tid] = W_in[tid]; sWout[tid] = W_out[tid]; }
    else if (tid < 72) {
        int i = tid - 64;
        sbin[i] = b_in[i];  sbout[i] = b_out[i];
        s1w[i] = ln1w[i];   s1b[i] = ln1b[i];
        s2w[i] = ln2w[i];   s2b[i] = ln2b[i];
        stha[i] = thetas_attn[i]; sthf[i] = thetas_ffn[i];
    }

    float th[8];
#pragma unroll
    for (int w = 0; w < 8; w++) th[w] = thetas_attn[w];

    // Prologue: 128 threads build 512 key rows (both heads).
#pragma unroll
    for (int rr = 0; rr < TT / 128; rr++) {
        int i = tid + rr * 128;
        const float* xr = x + ((size_t)(b * TT + i)) * 8;
        float4 xa = *reinterpret_cast<const float4*>(xr);
        float4 xb = *reinterpret_cast<const float4*>(xr + 4);
        float c[8];
        c[0] = __cosf(xa.x + th[0]);
        c[1] = __cosf(xa.y + th[1]);
        c[2] = __cosf(xa.z + th[2]);
        c[3] = __cosf(xa.w + th[3]);
        c[4] = __cosf(xb.x + th[4]);
        c[5] = __cosf(xb.y + th[5]);
        c[6] = __cosf(xb.z + th[6]);
        c[7] = __cosf(xb.w + th[7]);
        float o[8];
        qlayer_from_cos(c, o);
        ulonglong2 p0, p1;
        p0.x = pack2(o[0], o[4]);
        p0.y = pack2(o[1], o[5]);
        p1.x = pack2(o[2], o[6]);
        p1.y = pack2(o[3], o[7]);
        Kpk[i][0] = p0;
        Kpk[i][1] = p1;
    }
    __syncthreads();

    const int qloc = tid >> 1;          // 0..63
    const int half = tid & 1;           // key half
    const int qi   = chunk * QC + qloc; // query index in [0,512)

    // This thread's query, lane-packed; pre-scaled by 0.5*log2(e)
    const float SC = 0.72134752044f;
    const u64 SC2 = pack2(SC, SC);
    ulonglong2 qa = Kpk[qi][0];
    ulonglong2 qb = Kpk[qi][1];
    u64 qp0 = mul2(qa.x, SC2);
    u64 qp1 = mul2(qa.y, SC2);
    u64 qp2 = mul2(qb.x, SC2);
    u64 qp3 = mul2(qb.y, SC2);

    u64 acc0 = 0ull, acc1 = 0ull, acc2 = 0ull, acc3 = 0ull, dn = 0ull;

    const int k0 = half * (TT / 2);
    // |exp2 arg| <= 4 * 0.72 < 3 : no max subtraction needed.
#pragma unroll 8
    for (int k = k0; k < k0 + TT / 2; k++) {
        ulonglong2 ka = Kpk[k][0];
        ulonglong2 kb = Kpk[k][1];
        u64 s = mul2(qp0, ka.x);
        s = fma2(qp1, ka.y, s);
        s = fma2(qp2, kb.x, s);
        s = fma2(qp3, kb.y, s);
        float s0, s1; unpack2(s, s0, s1);
        float e0 = ex2(s0);
        float e1 = ex2(s1);
        u64 ep = pack2(e0, e1);
        acc0 = fma2(ep, ka.x, acc0);
        acc1 = fma2(ep, ka.y, acc1);
        acc2 = fma2(ep, kb.x, acc2);
        acc3 = fma2(ep, kb.y, acc3);
        dn = add2(dn, ep);
    }

    // Combine the two key-halves (lanes 2q, 2q+1 in same warp)
    acc0 = add2(acc0, __shfl_down_sync(0xffffffffu, acc0, 1));
    acc1 = add2(acc1, __shfl_down_sync(0xffffffffu, acc1, 1));
    acc2 = add2(acc2, __shfl_down_sync(0xffffffffu, acc2, 1));
    acc3 = add2(acc3, __shfl_down_sync(0xffffffffu, acc3, 1));
    dn   = add2(dn,   __shfl_down_sync(0xffffffffu, dn,   1));

    if (half == 0) {
        float d0, d1; unpack2(dn, d0, d1);
        float inv0 = __fdividef(1.0f, d0);
        float inv1 = __fdividef(1.0f, d1);

        float ctx[8];
        {
            float lo, hi;
            unpack2(acc0, lo, hi); ctx[0] = lo * inv0; ctx[4] = hi * inv1;
            unpack2(acc1, lo, hi); ctx[1] = lo * inv0; ctx[5] = hi * inv1;
            unpack2(acc2, lo, hi); ctx[2] = lo * inv0; ctx[6] = hi * inv1;
            unpack2(acc3, lo, hi); ctx[3] = lo * inv0; ctx[7] = hi * inv1;
        }

        const size_t row = (size_t)(b * TT + qi);
        const float* xr = x + row * 8;
        float xv[8];
        {
            float4 e = *reinterpret_cast<const float4*>(xr);
            float4 f = *reinterpret_cast<const float4*>(xr + 4);
            xv[0]=e.x; xv[1]=e.y; xv[2]=e.z; xv[3]=e.w;
            xv[4]=f.x; xv[5]=f.y; xv[6]=f.z; xv[7]=f.w;
        }

        // attn qlayer on ctx
        float c[8];
#pragma unroll
        for (int w = 0; w < 8; w++) c[w] = __cosf(ctx[w] + stha[w]);
        float ao[8];
        qlayer_from_cos(c, ao);

        // x1 = LN1(ao + x)
        float s[8], x1[8];
        float m = 0.0f;
#pragma unroll
        for (int w = 0; w < 8; w++) { s[w] = ao[w] + xv[w]; m += s[w]; }
        m *= 0.125f;
        float v = 0.0f;
#pragma unroll
        for (int w = 0; w < 8; w++) { float d = s[w] - m; v += d * d; }
        v *= 0.125f;
        float istd = rsqrtf(v + 1e-5f);
#pragma unroll
        for (int w = 0; w < 8; w++) x1[w] = (s[w] - m) * istd * s1w[w] + s1b[w];

        // hq = x1 @ W_in^T + b_in
        float hq[8];
#pragma unroll
        for (int i = 0; i < 8; i++) {
            float acc = sbin[i];
#pragma unroll
            for (int j = 0; j < 8; j++) acc += x1[j] * sWin[i * 8 + j];
            hq[i] = acc;
        }

        // ffn qlayer, wires [0,1,2,2,4,5,6,7]
        float cf[8];
        cf[0] = __cosf(hq[0] + sthf[0]);
        cf[1] = __cosf(hq[1] + sthf[1]);
        cf[2] = __cosf(hq[2] + hq[3] + sthf[2]);
        cf[3] = __cosf(sthf[3]);
        cf[4] = __cosf(hq[4] + sthf[4]);
        cf[5] = __cosf(hq[5] + sthf[5]);
        cf[6] = __cosf(hq[6] + sthf[6]);
        cf[7] = __cosf(hq[7] + sthf[7]);
        float qf[8];
        qlayer_from_cos(cf, qf);

        // ff = qf @ W_out^T + b_out; out = LN2(ff + x1)
        float s2[8];
        float m2 = 0.0f;
#pragma unroll
        for (int i = 0; i < 8; i++) {
            float acc = sbout[i];
#pragma unroll
            for (int j = 0; j < 8; j++) acc += qf[j] * sWout[i * 8 + j];
            s2[i] = acc + x1[i];
            m2 += s2[i];
        }
        m2 *= 0.125f;
        float v2 = 0.0f;
#pragma unroll
        for (int i = 0; i < 8; i++) { float d = s2[i] - m2; v2 += d * d; }
        v2 *= 0.125f;
        float istd2 = rsqrtf(v2 + 1e-5f);

        float res[8];
#pragma unroll
        for (int i = 0; i < 8; i++)
            res[i] = (s2[i] - m2) * istd2 * s2w[i] + s2b[i];

        float* orow = out + row * 8;
        *reinterpret_cast<float4*>(orow)     = make_float4(res[0], res[1], res[2], res[3]);
        *reinterpret_cast<float4*>(orow + 4) = make_float4(res[4], res[5], res[6], res[7]);
    }
}

extern "C" void kernel_launch(void* const* d_in, const int* in_sizes, int n_in,
                              void* d_out, int out_size) {
    const float* x           = (const float*)d_in[0];
    const float* thetas_attn = (const float*)d_in[1];
    const float* thetas_ffn  = (const float*)d_in[2];
    const float* W_in        = (const float*)d_in[3];
    const float* b_in        = (const float*)d_in[4];
    const float* W_out       = (const float*)d_in[5];
    const float* b_out       = (const float*)d_in[6];
    const float* ln1w        = (const float*)d_in[7];
    const float* ln1b        = (const float*)d_in[8];
    const float* ln2w        = (const float*)d_in[9];
    const float* ln2b        = (const float*)d_in[10];
    float* out = (float*)d_out;

    fused_kernel<<<NBLK, 128>>>(x, thetas_attn, thetas_ffn,
                                W_in, b_in, W_out, b_out,
                                ln1w, ln1b, ln2w, ln2b, out);
}